// round 6
// baseline (speedup 1.0000x reference)
#include <cuda_runtime.h>

#define NV 96
#define NNE 9216
#define LAT 256
#define OUTD 4656
#define ITERS 50
#define FULLW 0xffffffffu

__device__ float g_p_mu[16][LAT];
__device__ float g_p_ls[16][LAT];
__device__ float g_p_y[16][LAT];
__device__ float g_out[OUTD];
__device__ float g_xf[NNE];
__device__ float g_M[2][NNE];
__device__ int   g_scale[64];
__device__ unsigned g_arr[NV];     // monotonic barrier flags

// ---------------- MLP ----------------
__global__ void k_gemv1(const float* __restrict__ h, const float* __restrict__ Wmu,
                        const float* __restrict__ Wls) {
    __shared__ float sh[576];
    int c = blockIdx.x, mat = blockIdx.y, o = threadIdx.x;
    int k0 = c * 576;
    for (int kk = o; kk < 576; kk += 256) sh[kk] = h[k0 + kk];
    __syncthreads();
    const float* Wp = (mat ? Wls : Wmu) + (size_t)k0 * LAT + o;
    float acc = 0.f;
#pragma unroll 4
    for (int kk = 0; kk < 576; kk++) acc += sh[kk] * Wp[(size_t)kk * LAT];
    if (mat) g_p_ls[c][o] = acc; else g_p_mu[c][o] = acc;
}

__global__ void k_gemv2(const float* __restrict__ h, const float* __restrict__ Wd1,
                        const float* __restrict__ bmu) {
    __shared__ float sh[592];
    int c = blockIdx.x, o = threadIdx.x;
    int k0 = c * 592;
    for (int kk = o; kk < 592; kk += 256) {
        int k = k0 + kk;
        float v;
        if (k < NNE) v = h[k];
        else {
            int oo = k - NNE;
            v = bmu[oo];
#pragma unroll
            for (int cc = 0; cc < 16; cc++) v += g_p_mu[cc][oo];
        }
        sh[kk] = v;
    }
    __syncthreads();
    const float* Wp = Wd1 + (size_t)k0 * LAT + o;
    float acc = 0.f;
#pragma unroll 4
    for (int kk = 0; kk < 592; kk++) acc += sh[kk] * Wp[(size_t)kk * LAT];
    g_p_y[c][o] = acc;
}

__global__ void k_out(const float* __restrict__ Wd2, const float* __restrict__ bd2,
                      const float* __restrict__ bd1) {
    __shared__ float ys[LAT];
    int t = threadIdx.x;
    {
        float s = bd1[t];
#pragma unroll
        for (int c = 0; c < 16; c++) s += g_p_y[c][t];
        ys[t] = fmaxf(s, 0.f);
    }
    __syncthreads();
    int o = blockIdx.x * 256 + t;
    if (o < OUTD) {
        float acc = bd2[o];
#pragma unroll 4
        for (int k = 0; k < LAT; k++) acc += ys[k] * Wd2[(size_t)k * OUTD + o];
        g_out[o] = 1.f / (1.f + expf(-acc));
    }
}

// ---------------- helpers ----------------
__device__ __forceinline__ int triidx(int a, int b) {
    return a * NV - (a * (a - 1)) / 2 + (b - a);
}
__device__ __forceinline__ float rec_of(int i, int j) {
    int a = min(i, j), b = max(i, j);
    return g_out[triidx(a, b)];
}
__device__ __forceinline__ unsigned fmap(float x) {
    unsigned b = __float_as_uint(x);
    return b ^ ((unsigned)(((int)b) >> 31) | 0x80000000u);
}
__device__ __forceinline__ float funmap(unsigned k) {
    return __uint_as_float((k & 0x80000000u) ? (k ^ 0x80000000u) : ~k);
}

// ---------------- mega persistent kernel: setup + MPM + hung + loss ----------------
__global__ void __launch_bounds__(96, 1) k_mega(const float* __restrict__ adj,
                                                const float* __restrict__ bmu,
                                                const float* __restrict__ bls,
                                                float* __restrict__ out) {
    extern __shared__ float dyn[];
    float* Bs = dyn;               // 96*97
    float* Ms = dyn + NV * 97;     // 9216 (reused as xf in hung)
    __shared__ float sd[NV], snf[NV], sdr[NV], snfr[NV];
    __shared__ float As[NV], Ds[NV], xr[NV];
    __shared__ float red[3], redk[3];
    __shared__ float u_[97], vcol[97];
    __shared__ int p_[97], way_[97], rowof_[97], fl[NV], flB[NV];
    __shared__ int indsh[NV];
    __shared__ int sn0;
    __shared__ unsigned sbase;

    int tid = threadIdx.x, bid = blockIdx.x;
    if (tid == 0) sbase = *(volatile unsigned*)&g_arr[bid];

    // ---- setup (per-CTA local) ----
    {
        float drt = 0.f, nfrt = 0.f;
        for (int i = 0; i < NV; i++) {
            float r = rec_of(i, tid);
            nfrt += r;
            if (i == tid) drt = r;
        }
        sdr[tid] = drt;
        snfr[tid] = nfrt;
        float nft = 0.f;
        const float* arow = adj + tid * NV;
        for (int j = 0; j < NV; j++) nft += arow[j];
        sd[tid] = arow[tid];
        snf[tid] = nft;
    }
    __syncthreads();
    {
        float drt = sdr[tid];
        for (int i = 0; i < NV; i++)
            Bs[i * 97 + tid] = (i == tid) ? 0.f : rec_of(i, tid) * sdr[i] * drt;
        As[tid] = (bid == tid) ? 0.f : adj[bid * NV + tid] * sd[bid] * sd[tid];
        Ds[tid] = sd[bid] * sdr[tid] / (fabsf(snf[bid] - snfr[tid]) + 1.f);
        xr[tid] = 1.f / 96.f;
    }
    __syncthreads();
    unsigned base = sbase;

    // ---- MPM ----
    for (int it = 0; it < ITERS; it++) {
        int mb = it & 1;
        float xv = xr[tid];
        float m0 = 0.f, m1 = 0.f, m2 = 0.f, m3 = 0.f;
#pragma unroll
        for (int b = 0; b < NV; b += 4) {
            m0 = fmaxf(m0, xr[b] * Bs[b * 97 + tid]);
            m1 = fmaxf(m1, xr[b + 1] * Bs[(b + 1) * 97 + tid]);
            m2 = fmaxf(m2, xr[b + 2] * Bs[(b + 2) * 97 + tid]);
            m3 = fmaxf(m3, xr[b + 3] * Bs[(b + 3) * 97 + tid]);
        }
        __stcg(&g_M[mb][bid * NV + tid], fmaxf(fmaxf(m0, m1), fmaxf(m2, m3)));
        // grid barrier
        __syncthreads();
        unsigned tgt = base + (unsigned)(it + 1);
        if (tid == 0) { __threadfence(); *(volatile unsigned*)&g_arr[bid] = tgt; }
        {
            volatile unsigned* f = (volatile unsigned*)&g_arr[tid];
            while (*f < tgt) { }
        }
        __threadfence();
        __syncthreads();
        // stage M
        {
            const float4* src = (const float4*)&g_M[mb][0];
            float4* dst = (float4*)Ms;
            for (int i4 = tid; i4 < NNE / 4; i4 += NV) dst[i4] = __ldcg(src + i4);
        }
        __syncthreads();
        float sv = __int_as_float(*(volatile int*)&g_scale[it]);
        float inv = (sv > 0.f) ? 1.f / sv : 1.f;
        float a0 = xv * Ds[tid], a1 = 0.f, a2 = 0.f, a3 = 0.f;
#pragma unroll
        for (int j = 0; j < NV; j += 4) {
            a0 += As[j] * Ms[j * NV + tid];
            a1 += As[j + 1] * Ms[(j + 1) * NV + tid];
            a2 += As[j + 2] * Ms[(j + 2) * NV + tid];
            a3 += As[j + 3] * Ms[(j + 3) * NV + tid];
        }
        float acc = ((a0 + a1) + (a2 + a3)) * inv;
        xr[tid] = acc;
        float bm = acc;
        for (int off = 16; off; off >>= 1) bm = fmaxf(bm, __shfl_down_sync(FULLW, bm, off));
        if ((tid & 31) == 0) red[tid >> 5] = bm;
        __syncthreads();
        if (tid == 0)
            atomicMax(&g_scale[it + 1], __float_as_int(fmaxf(red[0], fmaxf(red[1], red[2]))));
    }
    __syncthreads();
    g_xf[bid * NV + tid] = xr[tid];
    // final barrier before hung
    {
        __syncthreads();
        unsigned tgt = base + (unsigned)(ITERS + 1);
        if (tid == 0) { __threadfence(); *(volatile unsigned*)&g_arr[bid] = tgt; }
        volatile unsigned* f = (volatile unsigned*)&g_arr[tid];
        while (*f < tgt) { }
        __threadfence();
        __syncthreads();
    }
    if (bid != 0) return;

    // ======== CTA 0: Hungarian fp32 ========
    float* xf = Ms;
    for (int idx = tid; idx < NNE; idx += NV) xf[idx] = __ldcg(&g_xf[idx]);
    if (tid < 97) { u_[tid] = 0.f; p_[tid] = 0; way_[tid] = 0; rowof_[tid] = 0; }
    __syncthreads();
    // Phase A: column reduction v[j] = min_i c[i,j], first-argmin row
    if (tid < NV) {
        float best = 1e30f; int bi = 1;
        for (int i2 = 0; i2 < NV; i2++) {
            float cv = -xf[i2 * NV + tid];
            if (cv < best) { best = cv; bi = i2 + 1; }
        }
        vcol[tid + 1] = best;
        rowof_[tid + 1] = bi;
    }
    __syncthreads();
    // Phase B: greedy assignment; way_ reused as rowmark
    if (tid == 0) {
        int cnt = 0;
        for (int j = 1; j <= NV; j++) {
            int i = rowof_[j];
            if (way_[i] == 0) { way_[i] = 1; p_[j] = i; }
        }
        for (int i = 1; i <= NV; i++) if (way_[i] == 0) fl[cnt++] = i;
        for (int i = 0; i <= NV; i++) way_[i] = 0;
        sn0 = cnt;
    }
    __syncthreads();
    // Phase B2: lapjv augmenting row reduction (2 passes, warp 0)
    if (tid < 32) {
        int lane = tid;
        const int J0 = 1 + lane, J1 = 33 + lane, J2 = 65 + lane;
        int nf = sn0;
        int* cur = fl;
        int* nxt = flB;
        for (int pass = 0; pass < 2 && nf > 0; pass++) {
            int nf2 = 0;
            for (int k = 0; k < nf; k++) {
                int i = cur[k];
                int chain = 0;
                while (true) {
                    chain++;
                    const float* crow = &xf[(i - 1) * NV];
                    // per-lane top-2 over 3 columns
                    float m1, m2; int j1, j2;
                    {
                        float h0 = -crow[J0 - 1] - vcol[J0];
                        m1 = h0; j1 = J0; m2 = 1e30f; j2 = J0;
                        float h1 = -crow[J1 - 1] - vcol[J1];
                        if (h1 < m1) { m2 = m1; j2 = j1; m1 = h1; j1 = J1; }
                        else { m2 = h1; j2 = J1; }
                        float h2 = -crow[J2 - 1] - vcol[J2];
                        if (h2 < m1) { m2 = m1; j2 = j1; m1 = h2; j1 = J2; }
                        else if (h2 < m2) { m2 = h2; j2 = J2; }
                    }
                    // warp top-2 reduce — GUARDED against out-of-range lanes
                    for (int off = 16; off; off >>= 1) {
                        float om1 = __shfl_down_sync(FULLW, m1, off);
                        float om2 = __shfl_down_sync(FULLW, m2, off);
                        int oj1 = __shfl_down_sync(FULLW, j1, off);
                        int oj2 = __shfl_down_sync(FULLW, j2, off);
                        if (lane + off < 32) {
                            if (om1 < m1) {
                                float c2; int cj2;
                                if (m1 < om2) { c2 = m1; cj2 = j1; }
                                else { c2 = om2; cj2 = oj2; }
                                m1 = om1; j1 = oj1; m2 = c2; j2 = cj2;
                            } else if (om1 < m2) {
                                m2 = om1; j2 = oj1;
                            }
                        }
                    }
                    m1 = __shfl_sync(FULLW, m1, 0); j1 = __shfl_sync(FULLW, j1, 0);
                    m2 = __shfl_sync(FULLW, m2, 0); j2 = __shfl_sync(FULLW, j2, 0);
                    bool strict = (m1 < m2);
                    int jt = j1;
                    int i0 = p_[jt];
                    if (!strict && i0 != 0) { jt = j2; i0 = p_[jt]; }
                    __syncwarp();
                    if (lane == 0) {
                        if (strict) vcol[j1] -= (m2 - m1);
                        u_[i] = m2;
                        p_[jt] = i;
                    }
                    __syncwarp();
                    if (i0 == 0) break;
                    if (strict && chain < 64) { i = i0; continue; }
                    if (lane == 0) nxt[nf2] = i0;
                    nf2++;
                    break;
                }
                __syncwarp();
            }
            nf = nf2;
            int* t = cur; cur = nxt; nxt = t;
            __syncwarp();
        }
    }
    __syncthreads();
    // rebuild free list from scratch (safety net)
    if (tid == 0) {
        for (int r = 0; r <= NV; r++) way_[r] = 0;
        for (int j = 1; j <= NV; j++) { int r = p_[j]; if (r) way_[r] = 1; }
        int cnt = 0;
        for (int r = 1; r <= NV; r++) if (!way_[r]) fl[cnt++] = r;
        sn0 = cnt;
        for (int r = 0; r <= NV; r++) way_[r] = 0;
    }
    __syncthreads();
    // Phase C: augmenting Dijkstra per remaining free row (warp 0)
    if (tid < 32) {
        int lane = tid;
        const int J0 = 1 + lane, J1 = 33 + lane, J2 = 65 + lane;
        int nf = sn0;
        for (int idx = 0; idx < nf; idx++) {
            int i = fl[idx];
            if (lane == 0) p_[0] = i;
            float mn0 = 1e30f, mn1 = 1e30f, mn2 = 1e30f;
            float vv0 = vcol[J0], vv1 = vcol[J1], vv2 = vcol[J2];
            bool us0 = false, us1 = false, us2 = false, usz = false;
            __syncwarp();
            int j0 = 0;
            while (true) {
                if (j0 == 0) { if (lane == 0) usz = true; }
                else if (j0 == J0) us0 = true;
                else if (j0 == J1) us1 = true;
                else if (j0 == J2) us2 = true;
                int i0 = p_[j0];
                float ui0 = u_[i0];
                const float* crow = &xf[(i0 - 1) * NV];
                unsigned k0 = ~0u, k1 = ~0u, k2 = ~0u;
                if (!us0) {
                    float cv = -crow[J0 - 1] - ui0 - vv0;
                    if (cv < mn0) { mn0 = cv; way_[J0] = j0; }
                    k0 = fmap(mn0);
                }
                if (!us1) {
                    float cv = -crow[J1 - 1] - ui0 - vv1;
                    if (cv < mn1) { mn1 = cv; way_[J1] = j0; }
                    k1 = fmap(mn1);
                }
                if (!us2) {
                    float cv = -crow[J2 - 1] - ui0 - vv2;
                    if (cv < mn2) { mn2 = cv; way_[J2] = j0; }
                    k2 = fmap(mn2);
                }
                unsigned lb = min(k0, min(k1, k2));
                unsigned g = __reduce_min_sync(FULLW, lb);
                float delta = funmap(g);
                unsigned b0 = __ballot_sync(FULLW, k0 == g);
                unsigned b1 = __ballot_sync(FULLW, k1 == g);
                unsigned b2 = __ballot_sync(FULLW, k2 == g);
                int j1s = b0 ? __ffs(b0) : (b1 ? 32 + __ffs(b1) : 64 + __ffs(b2));
                if (lane == 0 && usz) u_[p_[0]] += delta;
                if (us0) { u_[p_[J0]] += delta; vv0 -= delta; } else mn0 -= delta;
                if (us1) { u_[p_[J1]] += delta; vv1 -= delta; } else mn1 -= delta;
                if (us2) { u_[p_[J2]] += delta; vv2 -= delta; } else mn2 -= delta;
                __syncwarp();
                j0 = j1s;
                if (p_[j0] == 0) break;
            }
            if (lane == 0) {
                int jj = j0;
                while (jj) { int jn = way_[jj]; p_[jj] = p_[jn]; jj = jn; }
            }
            if (us0) vcol[J0] = vv0;
            if (us1) vcol[J1] = vv1;
            if (us2) vcol[J2] = vv2;
            __syncwarp();
        }
    }
    __syncthreads();
    if (tid < NV) indsh[tid] = p_[tid + 1] - 1;
    __syncthreads();

    // ---- final loss ----
    float s = 0.f;
    for (int idx = tid; idx < OUTD; idx += NV) {
        int i = (int)((193.0 - sqrt(193.0 * 193.0 - 8.0 * (double)idx)) * 0.5);
        if (i < 0) i = 0;
        if (i > 95) i = 95;
        while (i > 0 && (i * (193 - i)) / 2 > idx) i--;
        while (i < 95 && ((i + 1) * (192 - i)) / 2 <= idx) i++;
        int j = i + idx - (i * (193 - i)) / 2;
        float a = adj[indsh[i] * NV + indsh[j]];
        float t = g_out[idx];
        s += fmaxf(a, 0.f) - a * t + log1pf(expf(-fabsf(a)));
    }
    float w = 0.f;
    for (int o = tid; o < LAT; o += NV) {
        float smu = bmu[o], sls = bls[o];
#pragma unroll
        for (int c = 0; c < 16; c++) { smu += g_p_mu[c][o]; sls += g_p_ls[c][o]; }
        w += 1.f + sls - smu * smu - expf(sls);
    }
    for (int off = 16; off; off >>= 1) {
        s += __shfl_down_sync(FULLW, s, off);
        w += __shfl_down_sync(FULLW, w, off);
    }
    if ((tid & 31) == 0) { red[tid >> 5] = s; redk[tid >> 5] = w; }
    __syncthreads();
    if (tid == 0) {
        float S = red[0] + red[1] + red[2];
        float W = redk[0] + redk[1] + redk[2];
        out[0] = S / (float)OUTD + (-0.5f * W / (float)NNE);
    }
}

extern "C" void kernel_launch(void* const* d_in, const int* in_sizes, int n_in,
                              void* d_out, int out_size) {
    const float* h   = (const float*)d_in[0];
    const float* adj = (const float*)d_in[1];
    const float* Wmu = (const float*)d_in[2];
    const float* bmu = (const float*)d_in[3];
    const float* Wls = (const float*)d_in[4];
    const float* bls = (const float*)d_in[5];
    const float* Wd1 = (const float*)d_in[6];
    const float* bd1 = (const float*)d_in[7];
    const float* Wd2 = (const float*)d_in[8];
    const float* bd2 = (const float*)d_in[9];
    float* out = (float*)d_out;

    static int smem_set = 0;
    if (!smem_set) {
        cudaFuncSetAttribute(k_mega, cudaFuncAttributeMaxDynamicSharedMemorySize,
                             (NV * 97 + NNE) * 4);
        smem_set = 1;
    }

    dim3 g1(16, 2);
    k_gemv1<<<g1, 256>>>(h, Wmu, Wls);
    k_gemv2<<<16, 256>>>(h, Wd1, bmu);
    k_out<<<19, 256>>>(Wd2, bd2, bd1);
    k_mega<<<96, 96, (NV * 97 + NNE) * 4>>>(adj, bmu, bls, out);
}

// round 7
// speedup vs baseline: 3.5266x; 3.5266x over previous
#include <cuda_runtime.h>

#define NV 96
#define NNE 9216
#define LAT 256
#define OUTD 4656
#define ITERS 50
#define FULLW 0xffffffffu

__device__ float g_p_mu[16][LAT];
__device__ float g_p_ls[16][LAT];
__device__ float g_p_y[16][LAT];
__device__ float g_out[OUTD];
__device__ float g_xf[NNE];
__device__ float g_M[2][NNE];
__device__ int   g_scale[64];
__device__ unsigned g_arr[NV];     // monotonic barrier flags

// ---------------- MLP ----------------
__global__ void k_gemv1(const float* __restrict__ h, const float* __restrict__ Wmu,
                        const float* __restrict__ Wls) {
    __shared__ float sh[576];
    int c = blockIdx.x, mat = blockIdx.y, o = threadIdx.x;
    int k0 = c * 576;
    for (int kk = o; kk < 576; kk += 256) sh[kk] = h[k0 + kk];
    __syncthreads();
    const float* Wp = (mat ? Wls : Wmu) + (size_t)k0 * LAT + o;
    float acc = 0.f;
#pragma unroll 4
    for (int kk = 0; kk < 576; kk++) acc += sh[kk] * Wp[(size_t)kk * LAT];
    if (mat) g_p_ls[c][o] = acc; else g_p_mu[c][o] = acc;
}

__global__ void k_gemv2(const float* __restrict__ h, const float* __restrict__ Wd1,
                        const float* __restrict__ bmu) {
    __shared__ float sh[592];
    int c = blockIdx.x, o = threadIdx.x;
    int k0 = c * 592;
    for (int kk = o; kk < 592; kk += 256) {
        int k = k0 + kk;
        float v;
        if (k < NNE) v = h[k];
        else {
            int oo = k - NNE;
            v = bmu[oo];
#pragma unroll
            for (int cc = 0; cc < 16; cc++) v += g_p_mu[cc][oo];
        }
        sh[kk] = v;
    }
    __syncthreads();
    const float* Wp = Wd1 + (size_t)k0 * LAT + o;
    float acc = 0.f;
#pragma unroll 4
    for (int kk = 0; kk < 592; kk++) acc += sh[kk] * Wp[(size_t)kk * LAT];
    g_p_y[c][o] = acc;
}

__global__ void k_out(const float* __restrict__ Wd2, const float* __restrict__ bd2,
                      const float* __restrict__ bd1) {
    __shared__ float ys[LAT];
    int t = threadIdx.x;
    {
        float s = bd1[t];
#pragma unroll
        for (int c = 0; c < 16; c++) s += g_p_y[c][t];
        ys[t] = fmaxf(s, 0.f);
    }
    __syncthreads();
    int o = blockIdx.x * 256 + t;
    if (o < OUTD) {
        float acc = bd2[o];
#pragma unroll 4
        for (int k = 0; k < LAT; k++) acc += ys[k] * Wd2[(size_t)k * OUTD + o];
        g_out[o] = 1.f / (1.f + expf(-acc));
    }
}

// ---------------- helpers ----------------
__device__ __forceinline__ int triidx(int a, int b) {
    return a * NV - (a * (a - 1)) / 2 + (b - a);
}
__device__ __forceinline__ float rec_of(int i, int j) {
    int a = min(i, j), b = max(i, j);
    return g_out[triidx(a, b)];
}
__device__ __forceinline__ unsigned fmap(float x) {
    unsigned b = __float_as_uint(x);
    return b ^ ((unsigned)(((int)b) >> 31) | 0x80000000u);
}
__device__ __forceinline__ float funmap(unsigned k) {
    return __uint_as_float((k & 0x80000000u) ? (k ^ 0x80000000u) : ~k);
}

// ---------------- mega persistent kernel: setup + MPM + hung + loss ----------------
__global__ void __launch_bounds__(96, 1) k_mega(const float* __restrict__ adj,
                                                const float* __restrict__ bmu,
                                                const float* __restrict__ bls,
                                                float* __restrict__ out) {
    extern __shared__ float dyn[];
    float* Bs = dyn;               // 96*97
    float* Ms = dyn + NV * 97;     // 9216 (reused as xf in hung)
    __shared__ float sd[NV], snf[NV], sdr[NV], snfr[NV];
    __shared__ float As[NV], Ds[NV], xr[NV];
    __shared__ float red[3], redk[3];
    __shared__ float u_[97], vcol[97];
    __shared__ int p_[97], way_[97], rowof_[97], fl[NV];
    __shared__ int indsh[NV];
    __shared__ int sn0;
    __shared__ unsigned sbase;

    int tid = threadIdx.x, bid = blockIdx.x;
    if (tid == 0) sbase = *(volatile unsigned*)&g_arr[bid];

    // ---- setup (per-CTA local) ----
    {
        float drt = 0.f, nfrt = 0.f;
        for (int i = 0; i < NV; i++) {
            float r = rec_of(i, tid);
            nfrt += r;
            if (i == tid) drt = r;
        }
        sdr[tid] = drt;
        snfr[tid] = nfrt;
        float nft = 0.f;
        const float* arow = adj + tid * NV;
        for (int j = 0; j < NV; j++) nft += arow[j];
        sd[tid] = arow[tid];
        snf[tid] = nft;
    }
    __syncthreads();
    {
        float drt = sdr[tid];
        for (int i = 0; i < NV; i++)
            Bs[i * 97 + tid] = (i == tid) ? 0.f : rec_of(i, tid) * sdr[i] * drt;
        As[tid] = (bid == tid) ? 0.f : adj[bid * NV + tid] * sd[bid] * sd[tid];
        Ds[tid] = sd[bid] * sdr[tid] / (fabsf(snf[bid] - snfr[tid]) + 1.f);
        xr[tid] = 1.f / 96.f;
    }
    __syncthreads();
    unsigned base = sbase;

    // ---- MPM ----
    for (int it = 0; it < ITERS; it++) {
        int mb = it & 1;
        float xv = xr[tid];
        float m0 = 0.f, m1 = 0.f, m2 = 0.f, m3 = 0.f;
#pragma unroll
        for (int b = 0; b < NV; b += 4) {
            m0 = fmaxf(m0, xr[b] * Bs[b * 97 + tid]);
            m1 = fmaxf(m1, xr[b + 1] * Bs[(b + 1) * 97 + tid]);
            m2 = fmaxf(m2, xr[b + 2] * Bs[(b + 2) * 97 + tid]);
            m3 = fmaxf(m3, xr[b + 3] * Bs[(b + 3) * 97 + tid]);
        }
        __stcg(&g_M[mb][bid * NV + tid], fmaxf(fmaxf(m0, m1), fmaxf(m2, m3)));
        // grid barrier
        __syncthreads();
        unsigned tgt = base + (unsigned)(it + 1);
        if (tid == 0) { __threadfence(); *(volatile unsigned*)&g_arr[bid] = tgt; }
        {
            volatile unsigned* f = (volatile unsigned*)&g_arr[tid];
            while (*f < tgt) { }
        }
        __threadfence();
        __syncthreads();
        // stage M
        {
            const float4* src = (const float4*)&g_M[mb][0];
            float4* dst = (float4*)Ms;
            for (int i4 = tid; i4 < NNE / 4; i4 += NV) dst[i4] = __ldcg(src + i4);
        }
        __syncthreads();
        float sv = __int_as_float(*(volatile int*)&g_scale[it]);
        float inv = (sv > 0.f) ? 1.f / sv : 1.f;
        float a0 = xv * Ds[tid], a1 = 0.f, a2 = 0.f, a3 = 0.f;
#pragma unroll
        for (int j = 0; j < NV; j += 4) {
            a0 += As[j] * Ms[j * NV + tid];
            a1 += As[j + 1] * Ms[(j + 1) * NV + tid];
            a2 += As[j + 2] * Ms[(j + 2) * NV + tid];
            a3 += As[j + 3] * Ms[(j + 3) * NV + tid];
        }
        float acc = ((a0 + a1) + (a2 + a3)) * inv;
        xr[tid] = acc;
        float bm = acc;
        for (int off = 16; off; off >>= 1) bm = fmaxf(bm, __shfl_down_sync(FULLW, bm, off));
        if ((tid & 31) == 0) red[tid >> 5] = bm;
        __syncthreads();
        if (tid == 0)
            atomicMax(&g_scale[it + 1], __float_as_int(fmaxf(red[0], fmaxf(red[1], red[2]))));
    }
    __syncthreads();
    g_xf[bid * NV + tid] = xr[tid];
    // final barrier before hung
    {
        __syncthreads();
        unsigned tgt = base + (unsigned)(ITERS + 1);
        if (tid == 0) { __threadfence(); *(volatile unsigned*)&g_arr[bid] = tgt; }
        volatile unsigned* f = (volatile unsigned*)&g_arr[tid];
        while (*f < tgt) { }
        __threadfence();
        __syncthreads();
    }
    if (bid != 0) return;

    // ======== CTA 0: Hungarian fp32, absolute-dist Dijkstra ========
    float* xf = Ms;
    for (int idx = tid; idx < NNE; idx += NV) xf[idx] = __ldcg(&g_xf[idx]);
    if (tid < 97) { u_[tid] = 0.f; p_[tid] = 0; way_[tid] = 0; rowof_[tid] = 0; }
    __syncthreads();
    // Phase A: column reduction v[j] = min_i c[i,j], first-argmin row
    if (tid < NV) {
        float best = 1e30f; int bi = 1;
        for (int i2 = 0; i2 < NV; i2++) {
            float cv = -xf[i2 * NV + tid];
            if (cv < best) { best = cv; bi = i2 + 1; }
        }
        vcol[tid + 1] = best;
        rowof_[tid + 1] = bi;
    }
    __syncthreads();
    // Phase B: greedy assignment; way_ reused as rowmark
    if (tid == 0) {
        int cnt = 0;
        for (int j = 1; j <= NV; j++) {
            int i = rowof_[j];
            if (way_[i] == 0) { way_[i] = 1; p_[j] = i; }
        }
        for (int i = 1; i <= NV; i++) if (way_[i] == 0) fl[cnt++] = i;
        for (int i = 0; i <= NV; i++) way_[i] = 0;
        sn0 = cnt;
    }
    __syncthreads();
    // Phase C: absolute-dist Dijkstra augmentation (warp 0)
    // Invariants used: a column is scanned exactly once, at settlement, before any
    // dual update touches its row => scans use pre-Dijkstra u (uofp registers).
    // v/u updates collapse to (S_final - S_use) per used column, applied at the end.
    if (tid < 32) {
        int lane = tid;
        const int J0 = 1 + lane, J1 = 33 + lane, J2 = 65 + lane;
        float vst0 = vcol[J0], vst1 = vcol[J1], vst2 = vcol[J2];
        float uo0, uo1, uo2;
        {
            int r0 = p_[J0], r1 = p_[J1], r2 = p_[J2];
            uo0 = r0 ? u_[r0] : 0.f;
            uo1 = r1 ? u_[r1] : 0.f;
            uo2 = r2 ? u_[r2] : 0.f;
        }
        int nf = sn0;
        for (int idx = 0; idx < nf; idx++) {
            int i = fl[idx];
            if (lane == 0) p_[0] = i;
            float dist0 = 1e30f, dist1 = 1e30f, dist2 = 1e30f;
            float su0 = 0.f, su1 = 0.f, su2 = 0.f;
            bool us0 = false, us1 = false, us2 = false;
            float S = 0.f;
            float ui0 = 0.f;          // free rows always have u == 0
            int i0 = i;
            int j0 = 0;
            __syncwarp();
            while (true) {
                if (j0 == J0) { us0 = true; su0 = S; }
                else if (j0 == J1) { us1 = true; su1 = S; }
                else if (j0 == J2) { us2 = true; su2 = S; }
                const float* crow = &xf[(i0 - 1) * NV];
                unsigned k0 = ~0u, k1 = ~0u, k2 = ~0u;
                if (!us0) {
                    float cand = -crow[J0 - 1] - ui0 - vst0 + S;
                    if (cand < dist0) { dist0 = cand; way_[J0] = j0; }
                    k0 = fmap(dist0);
                }
                if (!us1) {
                    float cand = -crow[J1 - 1] - ui0 - vst1 + S;
                    if (cand < dist1) { dist1 = cand; way_[J1] = j0; }
                    k1 = fmap(dist1);
                }
                if (!us2) {
                    float cand = -crow[J2 - 1] - ui0 - vst2 + S;
                    if (cand < dist2) { dist2 = cand; way_[J2] = j0; }
                    k2 = fmap(dist2);
                }
                unsigned lb = min(k0, min(k1, k2));
                unsigned g = __reduce_min_sync(FULLW, lb);
                unsigned b0 = __ballot_sync(FULLW, k0 == g);
                unsigned b1 = __ballot_sync(FULLW, k1 == g);
                unsigned b2 = __ballot_sync(FULLW, k2 == g);
                int j1s = b0 ? __ffs(b0) : (b1 ? 32 + __ffs(b1) : 64 + __ffs(b2));
                S = funmap(g);
                int pj = p_[j1s];
                {
                    int owner = (j1s - 1) & 31;
                    int slot = (j1s - 1) >> 5;
                    float sel = (slot == 0) ? uo0 : ((slot == 1) ? uo1 : uo2);
                    ui0 = __shfl_sync(FULLW, sel, owner);
                }
                j0 = j1s;
                if (pj == 0) break;
                i0 = pj;
            }
            // dual updates (before rewiring, using old p_)
            float Sf = S;
            if (us0) { float d = Sf - su0; vst0 -= d; int r = p_[J0]; if (r) u_[r] += d; }
            if (us1) { float d = Sf - su1; vst1 -= d; int r = p_[J1]; if (r) u_[r] += d; }
            if (us2) { float d = Sf - su2; vst2 -= d; int r = p_[J2]; if (r) u_[r] += d; }
            if (lane == 0) u_[i] += Sf;
            __syncwarp();
            // rewire augmenting path
            if (lane == 0) {
                int jj = j0;
                while (jj) { int jn = way_[jj]; p_[jj] = p_[jn]; jj = jn; }
            }
            __syncwarp();
            // refresh uofp registers
            {
                int r0 = p_[J0], r1 = p_[J1], r2 = p_[J2];
                uo0 = r0 ? u_[r0] : 0.f;
                uo1 = r1 ? u_[r1] : 0.f;
                uo2 = r2 ? u_[r2] : 0.f;
            }
            __syncwarp();
        }
    }
    __syncthreads();
    if (tid < NV) indsh[tid] = p_[tid + 1] - 1;
    __syncthreads();

    // ---- final loss ----
    float s = 0.f;
    for (int idx = tid; idx < OUTD; idx += NV) {
        int i = (int)((193.0 - sqrt(193.0 * 193.0 - 8.0 * (double)idx)) * 0.5);
        if (i < 0) i = 0;
        if (i > 95) i = 95;
        while (i > 0 && (i * (193 - i)) / 2 > idx) i--;
        while (i < 95 && ((i + 1) * (192 - i)) / 2 <= idx) i++;
        int j = i + idx - (i * (193 - i)) / 2;
        float a = adj[indsh[i] * NV + indsh[j]];
        float t = g_out[idx];
        s += fmaxf(a, 0.f) - a * t + log1pf(expf(-fabsf(a)));
    }
    float w = 0.f;
    for (int o = tid; o < LAT; o += NV) {
        float smu = bmu[o], sls = bls[o];
#pragma unroll
        for (int c = 0; c < 16; c++) { smu += g_p_mu[c][o]; sls += g_p_ls[c][o]; }
        w += 1.f + sls - smu * smu - expf(sls);
    }
    for (int off = 16; off; off >>= 1) {
        s += __shfl_down_sync(FULLW, s, off);
        w += __shfl_down_sync(FULLW, w, off);
    }
    if ((tid & 31) == 0) { red[tid >> 5] = s; redk[tid >> 5] = w; }
    __syncthreads();
    if (tid == 0) {
        float S = red[0] + red[1] + red[2];
        float W = redk[0] + redk[1] + redk[2];
        out[0] = S / (float)OUTD + (-0.5f * W / (float)NNE);
    }
}

extern "C" void kernel_launch(void* const* d_in, const int* in_sizes, int n_in,
                              void* d_out, int out_size) {
    const float* h   = (const float*)d_in[0];
    const float* adj = (const float*)d_in[1];
    const float* Wmu = (const float*)d_in[2];
    const float* bmu = (const float*)d_in[3];
    const float* Wls = (const float*)d_in[4];
    const float* bls = (const float*)d_in[5];
    const float* Wd1 = (const float*)d_in[6];
    const float* bd1 = (const float*)d_in[7];
    const float* Wd2 = (const float*)d_in[8];
    const float* bd2 = (const float*)d_in[9];
    float* out = (float*)d_out;

    static int smem_set = 0;
    if (!smem_set) {
        cudaFuncSetAttribute(k_mega, cudaFuncAttributeMaxDynamicSharedMemorySize,
                             (NV * 97 + NNE) * 4);
        smem_set = 1;
    }

    dim3 g1(16, 2);
    k_gemv1<<<g1, 256>>>(h, Wmu, Wls);
    k_gemv2<<<16, 256>>>(h, Wd1, bmu);
    k_out<<<19, 256>>>(Wd2, bd2, bd1);
    k_mega<<<96, 96, (NV * 97 + NNE) * 4>>>(adj, bmu, bls, out);
}

// round 8
// speedup vs baseline: 3.7171x; 1.0540x over previous
#include <cuda_runtime.h>

#define NV 96
#define NNE 9216
#define LAT 256
#define OUTD 4656
#define ITERS 50
#define FULLW 0xffffffffu

__device__ float g_p_mu[16][LAT];
__device__ float g_p_ls[16][LAT];
__device__ float g_p_y[16][LAT];
__device__ float g_out[OUTD];
__device__ float g_xf[NNE];
__device__ float g_M[2][NNE];
__device__ int   g_scale[64];
__device__ unsigned g_arr[NV];     // monotonic barrier flags

// ---------------- MLP ----------------
__global__ void k_gemv1(const float* __restrict__ h, const float* __restrict__ Wmu,
                        const float* __restrict__ Wls) {
    __shared__ float sh[576];
    int c = blockIdx.x, mat = blockIdx.y, o = threadIdx.x;
    int k0 = c * 576;
    for (int kk = o; kk < 576; kk += 256) sh[kk] = h[k0 + kk];
    __syncthreads();
    const float* Wp = (mat ? Wls : Wmu) + (size_t)k0 * LAT + o;
    float acc = 0.f;
#pragma unroll 4
    for (int kk = 0; kk < 576; kk++) acc += sh[kk] * Wp[(size_t)kk * LAT];
    if (mat) g_p_ls[c][o] = acc; else g_p_mu[c][o] = acc;
}

__global__ void k_gemv2(const float* __restrict__ h, const float* __restrict__ Wd1,
                        const float* __restrict__ bmu) {
    __shared__ float sh[592];
    int c = blockIdx.x, o = threadIdx.x;
    int k0 = c * 592;
    for (int kk = o; kk < 592; kk += 256) {
        int k = k0 + kk;
        float v;
        if (k < NNE) v = h[k];
        else {
            int oo = k - NNE;
            v = bmu[oo];
#pragma unroll
            for (int cc = 0; cc < 16; cc++) v += g_p_mu[cc][oo];
        }
        sh[kk] = v;
    }
    __syncthreads();
    const float* Wp = Wd1 + (size_t)k0 * LAT + o;
    float acc = 0.f;
#pragma unroll 4
    for (int kk = 0; kk < 592; kk++) acc += sh[kk] * Wp[(size_t)kk * LAT];
    g_p_y[c][o] = acc;
}

__global__ void k_out(const float* __restrict__ Wd2, const float* __restrict__ bd2,
                      const float* __restrict__ bd1) {
    __shared__ float ys[LAT];
    int t = threadIdx.x;
    {
        float s = bd1[t];
#pragma unroll
        for (int c = 0; c < 16; c++) s += g_p_y[c][t];
        ys[t] = fmaxf(s, 0.f);
    }
    __syncthreads();
    int o = blockIdx.x * 256 + t;
    if (o < OUTD) {
        float acc = bd2[o];
#pragma unroll 4
        for (int k = 0; k < LAT; k++) acc += ys[k] * Wd2[(size_t)k * OUTD + o];
        g_out[o] = 1.f / (1.f + expf(-acc));
    }
}

// ---------------- helpers ----------------
__device__ __forceinline__ int triidx(int a, int b) {
    return a * NV - (a * (a - 1)) / 2 + (b - a);
}
__device__ __forceinline__ float rec_of(int i, int j) {
    int a = min(i, j), b = max(i, j);
    return g_out[triidx(a, b)];
}
__device__ __forceinline__ unsigned fmap(float x) {
    unsigned b = __float_as_uint(x);
    return b ^ ((unsigned)(((int)b) >> 31) | 0x80000000u);
}
__device__ __forceinline__ float funmap(unsigned k) {
    return __uint_as_float((k & 0x80000000u) ? (k ^ 0x80000000u) : ~k);
}

// ---------------- mega persistent kernel: setup + MPM + hung + loss ----------------
__global__ void __launch_bounds__(96, 1) k_mega(const float* __restrict__ adj,
                                                const float* __restrict__ bmu,
                                                const float* __restrict__ bls,
                                                float* __restrict__ out) {
    extern __shared__ float dyn[];
    float* Bs = dyn;               // 96*97
    float* Ms = dyn + NV * 97;     // 9216 (reused as xf in hung)
    __shared__ float sd[NV], snf[NV], sdr[NV], snfr[NV];
    __shared__ float As[NV], Ds[NV], xr[NV];
    __shared__ float red[3], redk[3];
    __shared__ float u_[97], vcol[97], rmin_[97];
    __shared__ int p_[97], way_[97], rowof_[97], rarg_[97], fl[NV], fl2[NV];
    __shared__ int indsh[NV];
    __shared__ int sn0;
    __shared__ unsigned sbase;

    int tid = threadIdx.x, bid = blockIdx.x;
    if (tid == 0) sbase = *(volatile unsigned*)&g_arr[bid];

    // ---- setup (per-CTA local) ----
    {
        float drt = 0.f, nfrt = 0.f;
        for (int i = 0; i < NV; i++) {
            float r = rec_of(i, tid);
            nfrt += r;
            if (i == tid) drt = r;
        }
        sdr[tid] = drt;
        snfr[tid] = nfrt;
        float nft = 0.f;
        const float* arow = adj + tid * NV;
        for (int j = 0; j < NV; j++) nft += arow[j];
        sd[tid] = arow[tid];
        snf[tid] = nft;
    }
    __syncthreads();
    {
        float drt = sdr[tid];
        for (int i = 0; i < NV; i++)
            Bs[i * 97 + tid] = (i == tid) ? 0.f : rec_of(i, tid) * sdr[i] * drt;
        As[tid] = (bid == tid) ? 0.f : adj[bid * NV + tid] * sd[bid] * sd[tid];
        Ds[tid] = sd[bid] * sdr[tid] / (fabsf(snf[bid] - snfr[tid]) + 1.f);
        xr[tid] = 1.f / 96.f;
    }
    __syncthreads();
    unsigned base = sbase;

    // ---- MPM ----
    for (int it = 0; it < ITERS; it++) {
        int mb = it & 1;
        float xv = xr[tid];
        float m0 = 0.f, m1 = 0.f, m2 = 0.f, m3 = 0.f;
#pragma unroll
        for (int b = 0; b < NV; b += 4) {
            m0 = fmaxf(m0, xr[b] * Bs[b * 97 + tid]);
            m1 = fmaxf(m1, xr[b + 1] * Bs[(b + 1) * 97 + tid]);
            m2 = fmaxf(m2, xr[b + 2] * Bs[(b + 2) * 97 + tid]);
            m3 = fmaxf(m3, xr[b + 3] * Bs[(b + 3) * 97 + tid]);
        }
        __stcg(&g_M[mb][bid * NV + tid], fmaxf(fmaxf(m0, m1), fmaxf(m2, m3)));
        // grid barrier
        __syncthreads();
        unsigned tgt = base + (unsigned)(it + 1);
        if (tid == 0) { __threadfence(); *(volatile unsigned*)&g_arr[bid] = tgt; }
        {
            volatile unsigned* f = (volatile unsigned*)&g_arr[tid];
            while (*f < tgt) { }
        }
        __threadfence();
        __syncthreads();
        // stage M
        {
            const float4* src = (const float4*)&g_M[mb][0];
            float4* dst = (float4*)Ms;
            for (int i4 = tid; i4 < NNE / 4; i4 += NV) dst[i4] = __ldcg(src + i4);
        }
        __syncthreads();
        float sv = __int_as_float(*(volatile int*)&g_scale[it]);
        float inv = (sv > 0.f) ? 1.f / sv : 1.f;
        float a0 = xv * Ds[tid], a1 = 0.f, a2 = 0.f, a3 = 0.f;
#pragma unroll
        for (int j = 0; j < NV; j += 4) {
            a0 += As[j] * Ms[j * NV + tid];
            a1 += As[j + 1] * Ms[(j + 1) * NV + tid];
            a2 += As[j + 2] * Ms[(j + 2) * NV + tid];
            a3 += As[j + 3] * Ms[(j + 3) * NV + tid];
        }
        float acc = ((a0 + a1) + (a2 + a3)) * inv;
        xr[tid] = acc;
        float bm = acc;
        for (int off = 16; off; off >>= 1) bm = fmaxf(bm, __shfl_down_sync(FULLW, bm, off));
        if ((tid & 31) == 0) red[tid >> 5] = bm;
        __syncthreads();
        if (tid == 0)
            atomicMax(&g_scale[it + 1], __float_as_int(fmaxf(red[0], fmaxf(red[1], red[2]))));
    }
    __syncthreads();
    g_xf[bid * NV + tid] = xr[tid];
    // final barrier before hung
    {
        __syncthreads();
        unsigned tgt = base + (unsigned)(ITERS + 1);
        if (tid == 0) { __threadfence(); *(volatile unsigned*)&g_arr[bid] = tgt; }
        volatile unsigned* f = (volatile unsigned*)&g_arr[tid];
        while (*f < tgt) { }
        __threadfence();
        __syncthreads();
    }
    if (bid != 0) return;

    // ======== CTA 0: Hungarian fp32, absolute-dist Dijkstra ========
    float* xf = Ms;
    for (int idx = tid; idx < NNE; idx += NV) xf[idx] = __ldcg(&g_xf[idx]);
    if (tid < 97) { u_[tid] = 0.f; p_[tid] = 0; way_[tid] = 0; rowof_[tid] = 0; }
    __syncthreads();
    // Phase A: column reduction v[j] = min_i c[i,j], first-argmin row
    if (tid < NV) {
        float best = 1e30f; int bi = 1;
        for (int i2 = 0; i2 < NV; i2++) {
            float cv = -xf[i2 * NV + tid];
            if (cv < best) { best = cv; bi = i2 + 1; }
        }
        vcol[tid + 1] = best;
        rowof_[tid + 1] = bi;
    }
    __syncthreads();
    // Phase B: greedy column assignment; way_ reused as rowmark
    if (tid == 0) {
        int cnt = 0;
        for (int j = 1; j <= NV; j++) {
            int i = rowof_[j];
            if (way_[i] == 0) { way_[i] = 1; p_[j] = i; }
        }
        for (int i = 1; i <= NV; i++) if (way_[i] == 0) fl[cnt++] = i;
        for (int i = 0; i <= NV; i++) way_[i] = 0;
        sn0 = cnt;
    }
    __syncthreads();
    // Phase B1: row reduction for rows (u_i = min_j c[i,j]-v_j), exact dual-feasible
    if (tid < NV) {
        int i = tid + 1;
        float best = 1e30f; int bj = 1;
        const float* crow = &xf[tid * NV];
        for (int j = 1; j <= NV; j++) {
            float cv = -crow[j - 1] - vcol[j];
            if (cv < best) { best = cv; bj = j; }
        }
        rmin_[i] = best;
        rarg_[i] = bj;
    }
    __syncthreads();
    if (tid == 0) {
        int cnt = 0;
        int n0 = sn0;
        for (int k = 0; k < n0; k++) {
            int i = fl[k];
            u_[i] = rmin_[i];
            int j = rarg_[i];
            if (p_[j] == 0) p_[j] = i;
            else fl2[cnt++] = i;
        }
        for (int k = 0; k < cnt; k++) fl[k] = fl2[k];
        sn0 = cnt;
    }
    __syncthreads();
    // Phase C: absolute-dist Dijkstra (warp 0), single-ballot argmin, p in registers
    if (tid < 32) {
        int lane = tid;
        const int J0 = 1 + lane, J1 = 33 + lane, J2 = 65 + lane;
        float vst0 = vcol[J0], vst1 = vcol[J1], vst2 = vcol[J2];
        int pr0 = p_[J0], pr1 = p_[J1], pr2 = p_[J2];
        float uo0 = pr0 ? u_[pr0] : 0.f;
        float uo1 = pr1 ? u_[pr1] : 0.f;
        float uo2 = pr2 ? u_[pr2] : 0.f;
        int nf = sn0;
        for (int idx = 0; idx < nf; idx++) {
            int i = fl[idx];
            if (lane == 0) p_[0] = i;
            float dist0 = 1e30f, dist1 = 1e30f, dist2 = 1e30f;
            float su0 = 0.f, su1 = 0.f, su2 = 0.f;
            bool us0 = false, us1 = false, us2 = false;
            float S = 0.f;
            float ui0 = u_[i];        // start row dual (nonzero after B1)
            int i0 = i;
            int j0 = 0;
            __syncwarp();
            while (true) {
                if (j0 == J0) { us0 = true; su0 = S; }
                else if (j0 == J1) { us1 = true; su1 = S; }
                else if (j0 == J2) { us2 = true; su2 = S; }
                const float* crow = &xf[(i0 - 1) * NV];
                unsigned k0 = ~0u, k1 = ~0u, k2 = ~0u;
                if (!us0) {
                    float cand = -crow[J0 - 1] - ui0 - vst0 + S;
                    if (cand < dist0) { dist0 = cand; way_[J0] = j0; }
                    k0 = fmap(dist0);
                }
                if (!us1) {
                    float cand = -crow[J1 - 1] - ui0 - vst1 + S;
                    if (cand < dist1) { dist1 = cand; way_[J1] = j0; }
                    k1 = fmap(dist1);
                }
                if (!us2) {
                    float cand = -crow[J2 - 1] - ui0 - vst2 + S;
                    if (cand < dist2) { dist2 = cand; way_[J2] = j0; }
                    k2 = fmap(dist2);
                }
                unsigned lb = min(k0, min(k1, k2));
                unsigned g = __reduce_min_sync(FULLW, lb);
                unsigned bb = __ballot_sync(FULLW, lb == g);
                int owner = __ffs(bb) - 1;
                int jl, pl; float ul;
                if (k0 == g) { jl = J0; pl = pr0; ul = uo0; }
                else if (k1 == g) { jl = J1; pl = pr1; ul = uo1; }
                else { jl = J2; pl = pr2; ul = uo2; }
                int j1s = __shfl_sync(FULLW, jl, owner);
                int pj  = __shfl_sync(FULLW, pl, owner);
                ui0     = __shfl_sync(FULLW, ul, owner);
                S = funmap(g);
                j0 = j1s;
                if (pj == 0) break;
                i0 = pj;
            }
            // dual updates (using pre-rewire rows in registers)
            float Sf = S;
            if (us0) { float d = Sf - su0; vst0 -= d; if (pr0) u_[pr0] += d; }
            if (us1) { float d = Sf - su1; vst1 -= d; if (pr1) u_[pr1] += d; }
            if (us2) { float d = Sf - su2; vst2 -= d; if (pr2) u_[pr2] += d; }
            if (lane == 0) {
                u_[i] += Sf;
                int jj = j0;
                while (jj) { int jn = way_[jj]; p_[jj] = p_[jn]; jj = jn; }
            }
            __syncwarp();
            pr0 = p_[J0]; pr1 = p_[J1]; pr2 = p_[J2];
            uo0 = pr0 ? u_[pr0] : 0.f;
            uo1 = pr1 ? u_[pr1] : 0.f;
            uo2 = pr2 ? u_[pr2] : 0.f;
            __syncwarp();
        }
    }
    __syncthreads();
    if (tid < NV) indsh[tid] = p_[tid + 1] - 1;
    __syncthreads();

    // ---- final loss ----
    float s = 0.f;
    for (int idx = tid; idx < OUTD; idx += NV) {
        int i = (int)((193.0 - sqrt(193.0 * 193.0 - 8.0 * (double)idx)) * 0.5);
        if (i < 0) i = 0;
        if (i > 95) i = 95;
        while (i > 0 && (i * (193 - i)) / 2 > idx) i--;
        while (i < 95 && ((i + 1) * (192 - i)) / 2 <= idx) i++;
        int j = i + idx - (i * (193 - i)) / 2;
        float a = adj[indsh[i] * NV + indsh[j]];
        float t = g_out[idx];
        s += fmaxf(a, 0.f) - a * t + log1pf(expf(-fabsf(a)));
    }
    float w = 0.f;
    for (int o = tid; o < LAT; o += NV) {
        float smu = bmu[o], sls = bls[o];
#pragma unroll
        for (int c = 0; c < 16; c++) { smu += g_p_mu[c][o]; sls += g_p_ls[c][o]; }
        w += 1.f + sls - smu * smu - expf(sls);
    }
    for (int off = 16; off; off >>= 1) {
        s += __shfl_down_sync(FULLW, s, off);
        w += __shfl_down_sync(FULLW, w, off);
    }
    if ((tid & 31) == 0) { red[tid >> 5] = s; redk[tid >> 5] = w; }
    __syncthreads();
    if (tid == 0) {
        float S = red[0] + red[1] + red[2];
        float W = redk[0] + redk[1] + redk[2];
        out[0] = S / (float)OUTD + (-0.5f * W / (float)NNE);
    }
}

extern "C" void kernel_launch(void* const* d_in, const int* in_sizes, int n_in,
                              void* d_out, int out_size) {
    const float* h   = (const float*)d_in[0];
    const float* adj = (const float*)d_in[1];
    const float* Wmu = (const float*)d_in[2];
    const float* bmu = (const float*)d_in[3];
    const float* Wls = (const float*)d_in[4];
    const float* bls = (const float*)d_in[5];
    const float* Wd1 = (const float*)d_in[6];
    const float* bd1 = (const float*)d_in[7];
    const float* Wd2 = (const float*)d_in[8];
    const float* bd2 = (const float*)d_in[9];
    float* out = (float*)d_out;

    static int smem_set = 0;
    if (!smem_set) {
        cudaFuncSetAttribute(k_mega, cudaFuncAttributeMaxDynamicSharedMemorySize,
                             (NV * 97 + NNE) * 4);
        smem_set = 1;
    }

    dim3 g1(16, 2);
    k_gemv1<<<g1, 256>>>(h, Wmu, Wls);
    k_gemv2<<<16, 256>>>(h, Wd1, bmu);
    k_out<<<19, 256>>>(Wd2, bd2, bd1);
    k_mega<<<96, 96, (NV * 97 + NNE) * 4>>>(adj, bmu, bls, out);
}

// round 9
// speedup vs baseline: 6.5408x; 1.7597x over previous
#include <cuda_runtime.h>

#define NV 96
#define NNE 9216
#define LAT 256
#define OUTD 4656
#define ITERS 50
#define FULLW 0xffffffffu
#define KINIT 0xFFFFFFFEu

__device__ float g_p_mu[16][LAT];
__device__ float g_p_ls[16][LAT];
__device__ float g_p_y[16][LAT];
__device__ float g_out[OUTD];
__device__ float g_xf[NNE];
__device__ float g_M[2][NNE];
__device__ int   g_scale[64];
__device__ unsigned g_arr[NV];     // monotonic barrier flags

// ---------------- MLP ----------------
__global__ void k_gemv1(const float* __restrict__ h, const float* __restrict__ Wmu,
                        const float* __restrict__ Wls) {
    __shared__ float sh[576];
    int c = blockIdx.x, mat = blockIdx.y, o = threadIdx.x;
    int k0 = c * 576;
    for (int kk = o; kk < 576; kk += 256) sh[kk] = h[k0 + kk];
    __syncthreads();
    const float* Wp = (mat ? Wls : Wmu) + (size_t)k0 * LAT + o;
    float acc = 0.f;
#pragma unroll 4
    for (int kk = 0; kk < 576; kk++) acc += sh[kk] * Wp[(size_t)kk * LAT];
    if (mat) g_p_ls[c][o] = acc; else g_p_mu[c][o] = acc;
}

__global__ void k_gemv2(const float* __restrict__ h, const float* __restrict__ Wd1,
                        const float* __restrict__ bmu) {
    __shared__ float sh[592];
    int c = blockIdx.x, o = threadIdx.x;
    int k0 = c * 592;
    for (int kk = o; kk < 592; kk += 256) {
        int k = k0 + kk;
        float v;
        if (k < NNE) v = h[k];
        else {
            int oo = k - NNE;
            v = bmu[oo];
#pragma unroll
            for (int cc = 0; cc < 16; cc++) v += g_p_mu[cc][oo];
        }
        sh[kk] = v;
    }
    __syncthreads();
    const float* Wp = Wd1 + (size_t)k0 * LAT + o;
    float acc = 0.f;
#pragma unroll 4
    for (int kk = 0; kk < 592; kk++) acc += sh[kk] * Wp[(size_t)kk * LAT];
    g_p_y[c][o] = acc;
}

__global__ void k_out(const float* __restrict__ Wd2, const float* __restrict__ bd2,
                      const float* __restrict__ bd1) {
    __shared__ float ys[LAT];
    int t = threadIdx.x;
    {
        float s = bd1[t];
#pragma unroll
        for (int c = 0; c < 16; c++) s += g_p_y[c][t];
        ys[t] = fmaxf(s, 0.f);
    }
    __syncthreads();
    int o = blockIdx.x * 256 + t;
    if (o < OUTD) {
        float acc = bd2[o];
#pragma unroll 4
        for (int k = 0; k < LAT; k++) acc += ys[k] * Wd2[(size_t)k * OUTD + o];
        g_out[o] = 1.f / (1.f + expf(-acc));
    }
}

// ---------------- helpers ----------------
__device__ __forceinline__ int triidx(int a, int b) {
    return a * NV - (a * (a - 1)) / 2 + (b - a);
}
__device__ __forceinline__ float rec_of(int i, int j) {
    int a = min(i, j), b = max(i, j);
    return g_out[triidx(a, b)];
}
__device__ __forceinline__ unsigned fmap(float x) {
    unsigned b = __float_as_uint(x);
    return b ^ ((unsigned)(((int)b) >> 31) | 0x80000000u);
}
__device__ __forceinline__ float funmap(unsigned k) {
    return __uint_as_float((k & 0x80000000u) ? (k ^ 0x80000000u) : ~k);
}

// ---------------- mega persistent kernel: setup + MPM + hung + loss ----------------
__global__ void __launch_bounds__(96, 1) k_mega(const float* __restrict__ adj,
                                                const float* __restrict__ bmu,
                                                const float* __restrict__ bls,
                                                float* __restrict__ out) {
    extern __shared__ float dyn[];
    float* Bs = dyn;               // 96*97
    float* Ms = dyn + NV * 97;     // 9216 (reused as xf in hung)
    __shared__ float sd[NV], snf[NV], sdr[NV], snfr[NV];
    __shared__ float As[NV], Ds[NV], xr[NV];
    __shared__ float red[3], redk[3];
    __shared__ float u_[97], vcol[97], rmin_[97];
    __shared__ int p_[97], way_[97], rowof_[97], rarg_[97], fl[NV], fl2[NV];
    __shared__ int indsh[NV];
    __shared__ int sn0;
    __shared__ unsigned sbase;

    int tid = threadIdx.x, bid = blockIdx.x;
    if (tid == 0) sbase = *(volatile unsigned*)&g_arr[bid];

    // ---- setup (per-CTA local) ----
    {
        float drt = 0.f, nfrt = 0.f;
        for (int i = 0; i < NV; i++) {
            float r = rec_of(i, tid);
            nfrt += r;
            if (i == tid) drt = r;
        }
        sdr[tid] = drt;
        snfr[tid] = nfrt;
        float nft = 0.f;
        const float* arow = adj + tid * NV;
        for (int j = 0; j < NV; j++) nft += arow[j];
        sd[tid] = arow[tid];
        snf[tid] = nft;
    }
    __syncthreads();
    {
        float drt = sdr[tid];
        for (int i = 0; i < NV; i++)
            Bs[i * 97 + tid] = (i == tid) ? 0.f : rec_of(i, tid) * sdr[i] * drt;
        As[tid] = (bid == tid) ? 0.f : adj[bid * NV + tid] * sd[bid] * sd[tid];
        Ds[tid] = sd[bid] * sdr[tid] / (fabsf(snf[bid] - snfr[tid]) + 1.f);
        xr[tid] = 1.f / 96.f;
    }
    __syncthreads();
    unsigned base = sbase;

    // ---- MPM ----
    for (int it = 0; it < ITERS; it++) {
        int mb = it & 1;
        float xv = xr[tid];
        float m0 = 0.f, m1 = 0.f, m2 = 0.f, m3 = 0.f;
#pragma unroll
        for (int b = 0; b < NV; b += 4) {
            m0 = fmaxf(m0, xr[b] * Bs[b * 97 + tid]);
            m1 = fmaxf(m1, xr[b + 1] * Bs[(b + 1) * 97 + tid]);
            m2 = fmaxf(m2, xr[b + 2] * Bs[(b + 2) * 97 + tid]);
            m3 = fmaxf(m3, xr[b + 3] * Bs[(b + 3) * 97 + tid]);
        }
        __stcg(&g_M[mb][bid * NV + tid], fmaxf(fmaxf(m0, m1), fmaxf(m2, m3)));
        // grid barrier
        __syncthreads();
        unsigned tgt = base + (unsigned)(it + 1);
        if (tid == 0) { __threadfence(); *(volatile unsigned*)&g_arr[bid] = tgt; }
        {
            volatile unsigned* f = (volatile unsigned*)&g_arr[tid];
            while (*f < tgt) { }
        }
        __threadfence();
        __syncthreads();
        // stage M
        {
            const float4* src = (const float4*)&g_M[mb][0];
            float4* dst = (float4*)Ms;
            for (int i4 = tid; i4 < NNE / 4; i4 += NV) dst[i4] = __ldcg(src + i4);
        }
        __syncthreads();
        float sv = __int_as_float(*(volatile int*)&g_scale[it]);
        float inv = (sv > 0.f) ? 1.f / sv : 1.f;
        float a0 = xv * Ds[tid], a1 = 0.f, a2 = 0.f, a3 = 0.f;
#pragma unroll
        for (int j = 0; j < NV; j += 4) {
            a0 += As[j] * Ms[j * NV + tid];
            a1 += As[j + 1] * Ms[(j + 1) * NV + tid];
            a2 += As[j + 2] * Ms[(j + 2) * NV + tid];
            a3 += As[j + 3] * Ms[(j + 3) * NV + tid];
        }
        float acc = ((a0 + a1) + (a2 + a3)) * inv;
        xr[tid] = acc;
        float bm = acc;
        for (int off = 16; off; off >>= 1) bm = fmaxf(bm, __shfl_down_sync(FULLW, bm, off));
        if ((tid & 31) == 0) red[tid >> 5] = bm;
        __syncthreads();
        if (tid == 0)
            atomicMax(&g_scale[it + 1], __float_as_int(fmaxf(red[0], fmaxf(red[1], red[2]))));
    }
    __syncthreads();
    g_xf[bid * NV + tid] = xr[tid];
    // final barrier before hung
    {
        __syncthreads();
        unsigned tgt = base + (unsigned)(ITERS + 1);
        if (tid == 0) { __threadfence(); *(volatile unsigned*)&g_arr[bid] = tgt; }
        volatile unsigned* f = (volatile unsigned*)&g_arr[tid];
        while (*f < tgt) { }
        __threadfence();
        __syncthreads();
    }
    if (bid != 0) return;

    // ======== CTA 0: Hungarian fp32, branchless absolute-dist Dijkstra ========
    float* xf = Ms;
    for (int idx = tid; idx < NNE; idx += NV) xf[idx] = __ldcg(&g_xf[idx]);
    if (tid < 97) { u_[tid] = 0.f; p_[tid] = 0; way_[tid] = 0; rowof_[tid] = 0; }
    __syncthreads();
    // Phase A: column reduction v[j] = min_i c[i,j], first-argmin row
    if (tid < NV) {
        float best = 1e30f; int bi = 1;
        for (int i2 = 0; i2 < NV; i2++) {
            float cv = -xf[i2 * NV + tid];
            if (cv < best) { best = cv; bi = i2 + 1; }
        }
        vcol[tid + 1] = best;
        rowof_[tid + 1] = bi;
    }
    __syncthreads();
    // Phase B: greedy column assignment; way_ reused as rowmark
    if (tid == 0) {
        int cnt = 0;
        for (int j = 1; j <= NV; j++) {
            int i = rowof_[j];
            if (way_[i] == 0) { way_[i] = 1; p_[j] = i; }
        }
        for (int i = 1; i <= NV; i++) if (way_[i] == 0) fl[cnt++] = i;
        for (int i = 0; i <= NV; i++) way_[i] = 0;
        sn0 = cnt;
    }
    __syncthreads();
    // Phase B1: row reduction for free rows (exact, dual-feasible)
    if (tid < NV) {
        int i = tid + 1;
        float best = 1e30f; int bj = 1;
        const float* crow = &xf[tid * NV];
        for (int j = 1; j <= NV; j++) {
            float cv = -crow[j - 1] - vcol[j];
            if (cv < best) { best = cv; bj = j; }
        }
        rmin_[i] = best;
        rarg_[i] = bj;
    }
    __syncthreads();
    if (tid == 0) {
        int cnt = 0;
        int n0 = sn0;
        for (int k = 0; k < n0; k++) {
            int i = fl[k];
            u_[i] = rmin_[i];
            int j = rarg_[i];
            if (p_[j] == 0) p_[j] = i;
            else fl2[cnt++] = i;
        }
        for (int k = 0; k < cnt; k++) fl[k] = fl2[k];
        sn0 = cnt;
    }
    __syncthreads();
    // Phase C: branchless absolute-dist Dijkstra (warp 0)
    if (tid < 32) {
        int lane = tid;
        const int J0 = 1 + lane, J1 = 33 + lane, J2 = 65 + lane;
        float vst0 = vcol[J0], vst1 = vcol[J1], vst2 = vcol[J2];
        int pr0 = p_[J0], pr1 = p_[J1], pr2 = p_[J2];
        float uo0 = pr0 ? u_[pr0] : 0.f;
        float uo1 = pr1 ? u_[pr1] : 0.f;
        float uo2 = pr2 ? u_[pr2] : 0.f;
        int nf = sn0;
        for (int idx = 0; idx < nf; idx++) {
            int i = fl[idx];
            if (lane == 0) p_[0] = i;
            unsigned k0 = KINIT, k1 = KINIT, k2 = KINIT;
            float su0 = 0.f, su1 = 0.f, su2 = 0.f;
            float S = 0.f;
            float ui0 = u_[i];
            int i0 = i;
            int j0 = 0;
            __syncwarp();
            while (true) {
                // settle-mark previous winner (branchless)
                bool h0 = (j0 == J0), h1 = (j0 == J1), h2 = (j0 == J2);
                su0 = h0 ? S : su0; su1 = h1 ? S : su1; su2 = h2 ? S : su2;
                k0 = h0 ? ~0u : k0; k1 = h1 ? ~0u : k1; k2 = h2 ? ~0u : k2;
                bool s0 = (k0 == ~0u), s1 = (k1 == ~0u), s2 = (k2 == ~0u);
                const float* crow = &xf[(i0 - 1) * NV];
                float c0 = (-crow[J0 - 1] - ui0 - vst0) + S;
                float c1 = (-crow[J1 - 1] - ui0 - vst1) + S;
                float c2 = (-crow[J2 - 1] - ui0 - vst2) + S;
                unsigned kc0 = fmap(c0), kc1 = fmap(c1), kc2 = fmap(c2);
                bool up0 = !s0 && (kc0 < k0);
                bool up1 = !s1 && (kc1 < k1);
                bool up2 = !s2 && (kc2 < k2);
                way_[up0 ? J0 : 0] = j0;       // way_[0] = trash, never read
                way_[up1 ? J1 : 0] = j0;
                way_[up2 ? J2 : 0] = j0;
                k0 = up0 ? kc0 : k0;
                k1 = up1 ? kc1 : k1;
                k2 = up2 ? kc2 : k2;
                unsigned lb = min(k0, min(k1, k2));
                unsigned g = __reduce_min_sync(FULLW, lb);
                unsigned bb = __ballot_sync(FULLW, lb == g);
                int owner = __ffs(bb) - 1;
                int pk; float ul;
                if (k0 == g)      { pk = J0 | (pr0 << 8); ul = uo0; }
                else if (k1 == g) { pk = J1 | (pr1 << 8); ul = uo1; }
                else              { pk = J2 | (pr2 << 8); ul = uo2; }
                pk = __shfl_sync(FULLW, pk, owner);
                ui0 = __shfl_sync(FULLW, ul, owner);
                S = funmap(g);
                j0 = pk & 0xff;
                int pj = pk >> 8;
                if (pj == 0) break;
                i0 = pj;
            }
            // dual updates (pre-rewire rows in registers); settled <=> key == ~0u
            float Sf = S;
            if (k0 == ~0u) { float d = Sf - su0; vst0 -= d; if (pr0) u_[pr0] += d; }
            if (k1 == ~0u) { float d = Sf - su1; vst1 -= d; if (pr1) u_[pr1] += d; }
            if (k2 == ~0u) { float d = Sf - su2; vst2 -= d; if (pr2) u_[pr2] += d; }
            __syncwarp();
            if (lane == 0) {
                u_[i] += Sf;
                int jj = j0;
                while (jj) { int jn = way_[jj]; p_[jj] = p_[jn]; jj = jn; }
            }
            __syncwarp();
            pr0 = p_[J0]; pr1 = p_[J1]; pr2 = p_[J2];
            uo0 = pr0 ? u_[pr0] : 0.f;
            uo1 = pr1 ? u_[pr1] : 0.f;
            uo2 = pr2 ? u_[pr2] : 0.f;
            __syncwarp();
        }
    }
    __syncthreads();
    if (tid < NV) indsh[tid] = p_[tid + 1] - 1;
    __syncthreads();

    // ---- final loss ----
    float s = 0.f;
    for (int idx = tid; idx < OUTD; idx += NV) {
        int i = (int)((193.0 - sqrt(193.0 * 193.0 - 8.0 * (double)idx)) * 0.5);
        if (i < 0) i = 0;
        if (i > 95) i = 95;
        while (i > 0 && (i * (193 - i)) / 2 > idx) i--;
        while (i < 95 && ((i + 1) * (192 - i)) / 2 <= idx) i++;
        int j = i + idx - (i * (193 - i)) / 2;
        float a = adj[indsh[i] * NV + indsh[j]];
        float t = g_out[idx];
        s += fmaxf(a, 0.f) - a * t + log1pf(expf(-fabsf(a)));
    }
    float w = 0.f;
    for (int o = tid; o < LAT; o += NV) {
        float smu = bmu[o], sls = bls[o];
#pragma unroll
        for (int c = 0; c < 16; c++) { smu += g_p_mu[c][o]; sls += g_p_ls[c][o]; }
        w += 1.f + sls - smu * smu - expf(sls);
    }
    for (int off = 16; off; off >>= 1) {
        s += __shfl_down_sync(FULLW, s, off);
        w += __shfl_down_sync(FULLW, w, off);
    }
    if ((tid & 31) == 0) { red[tid >> 5] = s; redk[tid >> 5] = w; }
    __syncthreads();
    if (tid == 0) {
        float S = red[0] + red[1] + red[2];
        float W = redk[0] + redk[1] + redk[2];
        out[0] = S / (float)OUTD + (-0.5f * W / (float)NNE);
    }
}

extern "C" void kernel_launch(void* const* d_in, const int* in_sizes, int n_in,
                              void* d_out, int out_size) {
    const float* h   = (const float*)d_in[0];
    const float* adj = (const float*)d_in[1];
    const float* Wmu = (const float*)d_in[2];
    const float* bmu = (const float*)d_in[3];
    const float* Wls = (const float*)d_in[4];
    const float* bls = (const float*)d_in[5];
    const float* Wd1 = (const float*)d_in[6];
    const float* bd1 = (const float*)d_in[7];
    const float* Wd2 = (const float*)d_in[8];
    const float* bd2 = (const float*)d_in[9];
    float* out = (float*)d_out;

    static int smem_set = 0;
    if (!smem_set) {
        cudaFuncSetAttribute(k_mega, cudaFuncAttributeMaxDynamicSharedMemorySize,
                             (NV * 97 + NNE) * 4);
        smem_set = 1;
    }

    dim3 g1(16, 2);
    k_gemv1<<<g1, 256>>>(h, Wmu, Wls);
    k_gemv2<<<16, 256>>>(h, Wd1, bmu);
    k_out<<<19, 256>>>(Wd2, bd2, bd1);
    k_mega<<<96, 96, (NV * 97 + NNE) * 4>>>(adj, bmu, bls, out);
}